// round 10
// baseline (speedup 1.0000x reference)
#include <cuda_runtime.h>
#include <cuda_bf16.h>
#include <cstdint>
#include <cstring>

// ---------------------------------------------------------------------------
// SyntaxGCN: GCNConv(512->256) + relu + global_mean_pool + linear(256->1) + sigmoid
// GEMM on HMMA (mma.sync m16n8k16 bf16) with bf16x2 split:
//   x*W ~= xh*Wh + xh*Wl + xl*Wh   (fp32 accumulate, rel err ~1e-7)
// R10: occupancy push — 64x128 block tile, warp tile 32x32, 3 CTAs/SM
//      (24 warps/SM vs 16), launch_bounds(256,3).
// ---------------------------------------------------------------------------

constexpr int N_NODES  = 20000;
constexpr int N_EDGES  = 320000;
constexpr int IN_DIM   = 512;
constexpr int HID      = 256;
constexpr int HID4     = HID / 4;
constexpr int N_GRAPHS = 256;
constexpr int CSR_CAP  = 128;

constexpr int TILE_M = 64;
constexpr int TILE_N = 128;
constexpr int TK     = 32;
constexpr int NCHUNK = IN_DIM / TK;        // 16
constexpr int SSTR   = 40;                 // smem row stride in bf16 (80B, LDSM conflict-free)
constexpr int MAT_A  = TILE_M * SSTR;      // 2560
constexpr int MAT_B  = TILE_N * SSTR;      // 5120
constexpr int OFF_ALO = MAT_A;             // 2560
constexpr int OFF_BHI = 2 * MAT_A;         // 5120
constexpr int OFF_BLO = 2 * MAT_A + MAT_B; // 10240
constexpr int STAGE  = 2 * MAT_A + 2 * MAT_B;  // 15360 bf16 = 30.7KB
constexpr int SMEM_BYTES = 2 * STAGE * (int)sizeof(__nv_bfloat16);  // 61440

// Scratch (device globals)
__device__ float4 g_hs[N_NODES * HID4];
__device__ float  g_dinv[N_NODES];
__device__ int    g_cnt[N_NODES];
__device__ int    g_csr[N_NODES * CSR_CAP];
__device__ float4 g_pooled[N_GRAPHS * HID4];
__device__ float  g_counts[N_GRAPHS];
__device__ uint4  g_xhi[N_NODES * IN_DIM / 8];
__device__ uint4  g_xlo[N_NODES * IN_DIM / 8];
__device__ uint4  g_wthi[HID * IN_DIM / 8];   // transposed: [n][k]
__device__ uint4  g_wtlo[HID * IN_DIM / 8];

// ---------------- helpers ---------------------------------------------------
__device__ __forceinline__ void red_add_v4(float4* addr, float4 v) {
    asm volatile("red.global.add.v4.f32 [%0], {%1,%2,%3,%4};"
                 :: "l"(addr), "f"(v.x), "f"(v.y), "f"(v.z), "f"(v.w)
                 : "memory");
}

__device__ __forceinline__ uint32_t smem_u32(const void* p) {
    uint32_t a;
    asm("{ .reg .u64 t; cvta.to.shared.u64 t, %1; cvt.u32.u64 %0, t; }" : "=r"(a) : "l"(p));
    return a;
}

__device__ __forceinline__ void cp16(void* dst_smem, const void* src) {
    asm volatile("cp.async.ca.shared.global [%0], [%1], 16;"
                 :: "r"(smem_u32(dst_smem)), "l"(src) : "memory");
}

__device__ __forceinline__ void ldsm_x4(uint32_t* r, uint32_t addr) {
    asm volatile("ldmatrix.sync.aligned.m8n8.x4.shared.b16 {%0,%1,%2,%3}, [%4];"
                 : "=r"(r[0]), "=r"(r[1]), "=r"(r[2]), "=r"(r[3]) : "r"(addr));
}

__device__ __forceinline__ uint32_t pack_bf16x2(float a, float b) {
    __nv_bfloat162 h2 = __floats2bfloat162_rn(a, b);
    uint32_t u; memcpy(&u, &h2, 4);
    return u;
}

__device__ __forceinline__ void split2(float v0, float v1, uint32_t& hi, uint32_t& lo) {
    __nv_bfloat16 h0 = __float2bfloat16_rn(v0);
    __nv_bfloat16 h1 = __float2bfloat16_rn(v1);
    hi = pack_bf16x2(v0, v1);
    lo = pack_bf16x2(v0 - __bfloat162float(h0), v1 - __bfloat162float(h1));
}

__device__ __forceinline__ void mma_bf16(float* c, const uint32_t* a,
                                         uint32_t b0, uint32_t b1) {
    asm volatile(
        "mma.sync.aligned.m16n8k16.row.col.f32.bf16.bf16.f32 "
        "{%0,%1,%2,%3}, {%4,%5,%6,%7}, {%8,%9}, {%0,%1,%2,%3};"
        : "+f"(c[0]), "+f"(c[1]), "+f"(c[2]), "+f"(c[3])
        : "r"(a[0]), "r"(a[1]), "r"(a[2]), "r"(a[3]), "r"(b0), "r"(b1));
}

// --- init -------------------------------------------------------------------
__global__ void init_kernel() {
    int i = blockIdx.x * blockDim.x + threadIdx.x;
    if (i < N_GRAPHS * HID4) g_pooled[i] = make_float4(0.f, 0.f, 0.f, 0.f);
    if (i < N_GRAPHS)        g_counts[i] = 0.f;
    if (i < N_NODES)         g_cnt[i] = 0;
}

__global__ void edge_bin_kernel(const int* __restrict__ ei) {
    int e = blockIdx.x * blockDim.x + threadIdx.x;
    if (e >= N_EDGES) return;
    int src = __ldg(&ei[e]);
    int dst = __ldg(&ei[N_EDGES + e]);
    int pos = atomicAdd(&g_cnt[dst], 1);
    if (pos < CSR_CAP) g_csr[dst * CSR_CAP + pos] = src;
}

__global__ void dinv_kernel() {
    int n = blockIdx.x * blockDim.x + threadIdx.x;
    if (n < N_NODES) g_dinv[n] = rsqrtf((float)(g_cnt[n] + 1));
}

// --- preconvert x -> bf16 hi/lo --------------------------------------------
__global__ __launch_bounds__(256) void convert_x_kernel(const float4* __restrict__ X4) {
    int i = blockIdx.x * blockDim.x + threadIdx.x;
    if (i >= N_NODES * IN_DIM / 4) return;
    float4 v = X4[i];
    uint2 hi, lo;
    split2(v.x, v.y, hi.x, lo.x);
    split2(v.z, v.w, hi.y, lo.y);
    ((uint2*)g_xhi)[i] = hi;
    ((uint2*)g_xlo)[i] = lo;
}

// --- preconvert W -> transposed bf16 hi/lo [n][k] ---------------------------
__global__ __launch_bounds__(256) void convert_w_kernel(const float4* __restrict__ W4) {
    int i = blockIdx.x * blockDim.x + threadIdx.x;
    if (i >= IN_DIM * HID / 4) return;
    int k  = i >> 6;
    int n4 = i & 63;
    float4 v = W4[i];
    float f[4] = {v.x, v.y, v.z, v.w};
    __nv_bfloat16* wh = (__nv_bfloat16*)g_wthi;
    __nv_bfloat16* wl = (__nv_bfloat16*)g_wtlo;
    #pragma unroll
    for (int j = 0; j < 4; j++) {
        int n = n4 * 4 + j;
        __nv_bfloat16 h = __float2bfloat16_rn(f[j]);
        wh[(size_t)n * IN_DIM + k] = h;
        wl[(size_t)n * IN_DIM + k] = __float2bfloat16_rn(f[j] - __bfloat162float(h));
    }
}

// --- tensor-core GEMM: hs = (x @ W) * dinv[row] ----------------------------
// 256 threads, 8 warps (2m x 4n), warp tile 32x32, 2-stage cp.async,
// 3 CTAs/SM (24 warps).
__global__ __launch_bounds__(256, 3) void gemm_mma_kernel() {
    extern __shared__ __nv_bfloat16 sm[];
    const uint32_t smaddr = smem_u32(sm);

    const int tid  = threadIdx.x;
    const int lane = tid & 31;
    const int wid  = tid >> 5;
    const int warp_m = wid & 1;     // 2 warps over M (32 rows each)
    const int warp_n = wid >> 1;    // 4 warps over N (32 cols each)
    const int quad  = lane >> 2;
    const int tig   = lane & 3;

    const int m0 = blockIdx.y * TILE_M;
    const int n0 = blockIdx.x * TILE_N;

    const __nv_bfloat16* xh = (const __nv_bfloat16*)g_xhi;
    const __nv_bfloat16* xl = (const __nv_bfloat16*)g_xlo;
    const __nv_bfloat16* wh = (const __nv_bfloat16*)g_wthi;
    const __nv_bfloat16* wl = (const __nv_bfloat16*)g_wtlo;

    float acc[2][4][4];
    #pragma unroll
    for (int i = 0; i < 2; i++)
        #pragma unroll
        for (int j = 0; j < 4; j++)
            #pragma unroll
            for (int c = 0; c < 4; c++) acc[i][j][c] = 0.f;

    // ldmatrix per-lane address components (in bf16 elements)
    const int a_row = lane & 15;
    const int a_k   = (lane & 16) ? 8 : 0;
    const int a_base = (warp_m * 32 + a_row) * SSTR + a_k;
    const int b_row = ((lane >> 4) & 1) * 8 + (lane & 7);
    const int b_k   = (lane & 8) ? 8 : 0;
    const int b_base = (warp_n * 32 + b_row) * SSTR + b_k;

    // loader: A 64 rows (tid 0..255 -> row=tid>>2, c=tid&3), B 128 rows x2
    const int a_lrow = tid >> 2;          // 0..63
    const int a_lc   = tid & 3;
    int gra = m0 + a_lrow; if (gra >= N_NODES) gra = 0;
    const size_t aoff0 = (size_t)gra * IN_DIM + a_lc * 8;
    const int a_doff = a_lrow * SSTR + a_lc * 8;

    auto load_stage = [&](int s, int chunk) {
        const int k0 = chunk * TK;
        __nv_bfloat16* st = sm + s * STAGE;
        cp16(st + a_doff,           xh + aoff0 + k0);
        cp16(st + OFF_ALO + a_doff, xl + aoff0 + k0);
        #pragma unroll
        for (int r = 0; r < 2; r++) {
            int idx  = tid + 256 * r;
            int row  = idx >> 2;          // 0..127
            int c    = idx & 3;
            size_t boff = (size_t)(n0 + row) * IN_DIM + k0 + c * 8;
            __nv_bfloat16* d = st + row * SSTR + c * 8;
            cp16(d + OFF_BHI, wh + boff);
            cp16(d + OFF_BLO, wl + boff);
        }
    };

    load_stage(0, 0);
    asm volatile("cp.async.commit_group;" ::: "memory");

    for (int chunk = 0; chunk < NCHUNK; chunk++) {
        if (chunk + 1 < NCHUNK) load_stage((chunk + 1) & 1, chunk + 1);
        asm volatile("cp.async.commit_group;" ::: "memory");
        asm volatile("cp.async.wait_group 1;" ::: "memory");
        __syncthreads();

        const uint32_t stg = smaddr + (uint32_t)(chunk & 1) * (STAGE * 2);

        #pragma unroll
        for (int ks = 0; ks < 2; ks++) {
            const int kb = ks * 16;
            uint32_t ahi[2][4], alo[2][4];
            #pragma unroll
            for (int i = 0; i < 2; i++) {
                uint32_t aa = stg + (uint32_t)(a_base + i * 16 * SSTR + kb) * 2;
                ldsm_x4(ahi[i], aa);
                ldsm_x4(alo[i], aa + OFF_ALO * 2);
            }
            #pragma unroll
            for (int p = 0; p < 2; p++) {
                uint32_t ba = stg + (uint32_t)(b_base + p * 16 * SSTR + kb) * 2;
                uint32_t bh[4], bl[4];
                ldsm_x4(bh, ba + OFF_BHI * 2);
                ldsm_x4(bl, ba + OFF_BLO * 2);
                // pass-major: 4 independent accs per pass
                mma_bf16(acc[0][2 * p],     ahi[0], bh[0], bh[1]);   // xh*Wh
                mma_bf16(acc[1][2 * p],     ahi[1], bh[0], bh[1]);
                mma_bf16(acc[0][2 * p + 1], ahi[0], bh[2], bh[3]);
                mma_bf16(acc[1][2 * p + 1], ahi[1], bh[2], bh[3]);
                mma_bf16(acc[0][2 * p],     ahi[0], bl[0], bl[1]);   // xh*Wl
                mma_bf16(acc[1][2 * p],     ahi[1], bl[0], bl[1]);
                mma_bf16(acc[0][2 * p + 1], ahi[0], bl[2], bl[3]);
                mma_bf16(acc[1][2 * p + 1], ahi[1], bl[2], bl[3]);
                mma_bf16(acc[0][2 * p],     alo[0], bh[0], bh[1]);   // xl*Wh
                mma_bf16(acc[1][2 * p],     alo[1], bh[0], bh[1]);
                mma_bf16(acc[0][2 * p + 1], alo[0], bh[2], bh[3]);
                mma_bf16(acc[1][2 * p + 1], alo[1], bh[2], bh[3]);
            }
        }
        __syncthreads();
    }

    // ---- epilogue: scale by dinv, store hs only --------------------------
    #pragma unroll
    for (int i = 0; i < 2; i++) {
        const int r0 = m0 + warp_m * 32 + i * 16 + quad;
        const int r1 = r0 + 8;
        const bool v0 = r0 < N_NODES;
        const bool v1 = r1 < N_NODES;
        const float d0 = v0 ? g_dinv[r0] : 0.f;
        const float d1 = v1 ? g_dinv[r1] : 0.f;
        #pragma unroll
        for (int j = 0; j < 4; j++) {
            const int col = n0 + warp_n * 32 + j * 8 + tig * 2;
            if (v0) {
                float2 s = make_float2(acc[i][j][0] * d0, acc[i][j][1] * d0);
                *(float2*)((float*)g_hs + (size_t)r0 * HID + col) = s;
            }
            if (v1) {
                float2 s = make_float2(acc[i][j][2] * d1, acc[i][j][3] * d1);
                *(float2*)((float*)g_hs + (size_t)r1 * HID + col) = s;
            }
        }
    }
}

// --- gather + relu + pool: one node per 64 threads, unroll 8 ----------------
__global__ __launch_bounds__(256) void gather_pool_kernel(
    const int* __restrict__ batch, const float* __restrict__ b)
{
    int t = blockIdx.x * blockDim.x + threadIdx.x;
    int n = t >> 6;
    int lane = t & 63;
    if (n >= N_NODES) return;

    int cnt = g_cnt[n];
    if (cnt > CSR_CAP) cnt = CSR_CAP;
    const int* lst = g_csr + n * CSR_CAP;

    float4 a = g_hs[(size_t)n * HID4 + lane];   // self loop
    int i = 0;
    for (; i + 8 <= cnt; i += 8) {
        int s[8];
        #pragma unroll
        for (int q = 0; q < 8; q++) s[q] = __ldg(&lst[i + q]);
        float4 v[8];
        #pragma unroll
        for (int q = 0; q < 8; q++) v[q] = __ldg(&g_hs[(size_t)s[q] * HID4 + lane]);
        #pragma unroll
        for (int q = 0; q < 8; q++) {
            a.x += v[q].x; a.y += v[q].y; a.z += v[q].z; a.w += v[q].w;
        }
    }
    for (; i < cnt; i++) {
        int s = __ldg(&lst[i]);
        float4 v = __ldg(&g_hs[(size_t)s * HID4 + lane]);
        a.x += v.x; a.y += v.y; a.z += v.z; a.w += v.w;
    }

    float d = g_dinv[n];
    float4 bb = __ldg((const float4*)b + lane);
    float4 v;
    v.x = fmaxf(fmaf(a.x, d, bb.x), 0.f);
    v.y = fmaxf(fmaf(a.y, d, bb.y), 0.f);
    v.z = fmaxf(fmaf(a.z, d, bb.z), 0.f);
    v.w = fmaxf(fmaf(a.w, d, bb.w), 0.f);

    int g = __ldg(&batch[n]);
    red_add_v4(&g_pooled[(size_t)g * HID4 + lane], v);
    if (lane == 0) atomicAdd(&g_counts[g], 1.f);
}

// --- head --------------------------------------------------------------------
__global__ void head_kernel(
    const float* __restrict__ lin_w, const float* __restrict__ lin_b,
    float* __restrict__ out)
{
    __shared__ float red[256];
    int g = blockIdx.x;
    int t = threadIdx.x;
    const float* pooled = (const float*)g_pooled;
    red[t] = pooled[g * HID + t] * __ldg(&lin_w[t]);
    __syncthreads();
    #pragma unroll
    for (int s = 128; s > 0; s >>= 1) {
        if (t < s) red[t] += red[t + s];
        __syncthreads();
    }
    if (t == 0) {
        float cnt = fmaxf(g_counts[g], 1.f);
        float z = red[0] / cnt + __ldg(&lin_b[0]);
        out[g] = 1.f / (1.f + expf(-z));
    }
}

// ---------------------------------------------------------------------------
extern "C" void kernel_launch(void* const* d_in, const int* in_sizes, int n_in,
                              void* d_out, int out_size) {
    const float* x     = (const float*)d_in[0];
    const int*   ei    = (const int*)d_in[1];
    const int*   batch = (const int*)d_in[2];
    const float* W     = (const float*)d_in[3];
    const float* b     = (const float*)d_in[4];
    const float* lin_w = (const float*)d_in[5];
    const float* lin_b = (const float*)d_in[6];
    float*       out   = (float*)d_out;

    static bool attr_set = false;
    if (!attr_set) {
        cudaFuncSetAttribute(gemm_mma_kernel,
                             cudaFuncAttributeMaxDynamicSharedMemorySize, SMEM_BYTES);
        attr_set = true;
    }

    init_kernel<<<(N_GRAPHS * HID + 255) / 256, 256>>>();
    edge_bin_kernel<<<(N_EDGES + 255) / 256, 256>>>(ei);
    dinv_kernel<<<(N_NODES + 255) / 256, 256>>>();
    convert_x_kernel<<<(N_NODES * IN_DIM / 4 + 255) / 256, 256>>>((const float4*)x);
    convert_w_kernel<<<(IN_DIM * HID / 4 + 255) / 256, 256>>>((const float4*)W);
    gemm_mma_kernel<<<dim3(HID / TILE_N, (N_NODES + TILE_M - 1) / TILE_M),
                      256, SMEM_BYTES>>>();
    gather_pool_kernel<<<(N_NODES * 64 + 255) / 256, 256>>>(batch, b);
    head_kernel<<<N_GRAPHS, 256>>>(lin_w, lin_b, out);
}

// round 11
// speedup vs baseline: 1.0984x; 1.0984x over previous
#include <cuda_runtime.h>
#include <cuda_bf16.h>
#include <cuda_fp16.h>
#include <cstdint>
#include <cstring>

// ---------------------------------------------------------------------------
// SyntaxGCN: GCNConv(512->256) + relu + global_mean_pool + linear(256->1) + sigmoid
// R11: 2-pass fp16 GEMM.  xs = x*dinv split into fp16 hi+lo (~22 bits exact),
//      W single fp16:  hs = xh@Wf + xl@Wf.  Error = x@(W-Wf) ~ 5e-4 element,
//      averaged down by pooling/head => final ~1e-4 << 1e-3 tolerance.
//      MMA count 2/3 of the bf16 3-pass scheme (mma.sync is the ceiling).
// ---------------------------------------------------------------------------

constexpr int N_NODES  = 20000;
constexpr int N_EDGES  = 320000;
constexpr int IN_DIM   = 512;
constexpr int HID      = 256;
constexpr int HID4     = HID / 4;
constexpr int N_GRAPHS = 256;
constexpr int CSR_CAP  = 128;

constexpr int TILE_M = 128;
constexpr int TILE_N = 128;
constexpr int TK     = 32;
constexpr int NCHUNK = IN_DIM / TK;        // 16
constexpr int SSTR   = 40;                 // smem row stride in f16 (80B, LDSM conflict-free)
constexpr int MAT    = TILE_M * SSTR;      // 5120
constexpr int OFF_ALO = MAT;
constexpr int OFF_B   = 2 * MAT;
constexpr int STAGE  = 3 * MAT;            // 15360 f16 = 30.7KB
constexpr int SMEM_BYTES = 2 * STAGE * (int)sizeof(__half);  // 61440

// Scratch (device globals)
__device__ float4 g_hs[N_NODES * HID4];
__device__ float  g_dinv[N_NODES];
__device__ int    g_cnt[N_NODES];
__device__ int    g_csr[N_NODES * CSR_CAP];
__device__ float4 g_pooled[N_GRAPHS * HID4];
__device__ float  g_counts[N_GRAPHS];
__device__ uint4  g_xhi[N_NODES * IN_DIM / 8];   // fp16, pre-scaled by dinv
__device__ uint4  g_xlo[N_NODES * IN_DIM / 8];   // fp16 residual
__device__ uint4  g_wt[HID * IN_DIM / 8];        // fp16, transposed [n][k]

// ---------------- helpers ---------------------------------------------------
__device__ __forceinline__ void red_add_v4(float4* addr, float4 v) {
    asm volatile("red.global.add.v4.f32 [%0], {%1,%2,%3,%4};"
                 :: "l"(addr), "f"(v.x), "f"(v.y), "f"(v.z), "f"(v.w)
                 : "memory");
}

__device__ __forceinline__ uint32_t smem_u32(const void* p) {
    uint32_t a;
    asm("{ .reg .u64 t; cvta.to.shared.u64 t, %1; cvt.u32.u64 %0, t; }" : "=r"(a) : "l"(p));
    return a;
}

__device__ __forceinline__ void cp16(void* dst_smem, const void* src) {
    asm volatile("cp.async.ca.shared.global [%0], [%1], 16;"
                 :: "r"(smem_u32(dst_smem)), "l"(src) : "memory");
}

__device__ __forceinline__ void ldsm_x4(uint32_t* r, uint32_t addr) {
    asm volatile("ldmatrix.sync.aligned.m8n8.x4.shared.b16 {%0,%1,%2,%3}, [%4];"
                 : "=r"(r[0]), "=r"(r[1]), "=r"(r[2]), "=r"(r[3]) : "r"(addr));
}

// split 2 scaled floats into fp16 hi pair + fp16 residual pair
__device__ __forceinline__ void split2h(float v0, float v1, uint32_t& hi, uint32_t& lo) {
    __half h0 = __float2half_rn(v0);
    __half h1 = __float2half_rn(v1);
    __half2 hh = __halves2half2(h0, h1);
    memcpy(&hi, &hh, 4);
    __half2 ll = __halves2half2(__float2half_rn(v0 - __half2float(h0)),
                                __float2half_rn(v1 - __half2float(h1)));
    memcpy(&lo, &ll, 4);
}

__device__ __forceinline__ void mma_f16(float* c, const uint32_t* a,
                                        uint32_t b0, uint32_t b1) {
    asm volatile(
        "mma.sync.aligned.m16n8k16.row.col.f32.f16.f16.f32 "
        "{%0,%1,%2,%3}, {%4,%5,%6,%7}, {%8,%9}, {%0,%1,%2,%3};"
        : "+f"(c[0]), "+f"(c[1]), "+f"(c[2]), "+f"(c[3])
        : "r"(a[0]), "r"(a[1]), "r"(a[2]), "r"(a[3]), "r"(b0), "r"(b1));
}

// --- init -------------------------------------------------------------------
__global__ void init_kernel() {
    int i = blockIdx.x * blockDim.x + threadIdx.x;
    if (i < N_GRAPHS * HID4) g_pooled[i] = make_float4(0.f, 0.f, 0.f, 0.f);
    if (i < N_GRAPHS)        g_counts[i] = 0.f;
    if (i < N_NODES)         g_cnt[i] = 0;
}

__global__ void edge_bin_kernel(const int* __restrict__ ei) {
    int e = blockIdx.x * blockDim.x + threadIdx.x;
    if (e >= N_EDGES) return;
    int src = __ldg(&ei[e]);
    int dst = __ldg(&ei[N_EDGES + e]);
    int pos = atomicAdd(&g_cnt[dst], 1);
    if (pos < CSR_CAP) g_csr[dst * CSR_CAP + pos] = src;
}

__global__ void dinv_kernel() {
    int n = blockIdx.x * blockDim.x + threadIdx.x;
    if (n < N_NODES) g_dinv[n] = rsqrtf((float)(g_cnt[n] + 1));
}

// --- preconvert xs = x*dinv -> fp16 hi/lo (dinv folded: needs dinv first) ---
__global__ __launch_bounds__(256) void convert_x_kernel(const float4* __restrict__ X4) {
    int i = blockIdx.x * blockDim.x + threadIdx.x;
    if (i >= N_NODES * IN_DIM / 4) return;
    int row = i >> 7;                       // IN_DIM/4 = 128 float4 per row
    float d = __ldg(&g_dinv[row]);
    float4 v = X4[i];
    uint2 hi, lo;
    split2h(v.x * d, v.y * d, hi.x, lo.x);
    split2h(v.z * d, v.w * d, hi.y, lo.y);
    ((uint2*)g_xhi)[i] = hi;
    ((uint2*)g_xlo)[i] = lo;
}

// --- preconvert W -> transposed fp16 [n][k] ---------------------------------
__global__ __launch_bounds__(256) void convert_w_kernel(const float4* __restrict__ W4) {
    int i = blockIdx.x * blockDim.x + threadIdx.x;
    if (i >= IN_DIM * HID / 4) return;
    int k  = i >> 6;
    int n4 = i & 63;
    float4 v = W4[i];
    float f[4] = {v.x, v.y, v.z, v.w};
    __half* wt = (__half*)g_wt;
    #pragma unroll
    for (int j = 0; j < 4; j++)
        wt[(size_t)(n4 * 4 + j) * IN_DIM + k] = __float2half_rn(f[j]);
}

// --- tensor-core GEMM: hs = xs @ W (dinv already folded into xs) ------------
// 256 threads, 8 warps (4m x 2n), warp tile 32x64, 2-stage cp.async, ldmatrix.
__global__ __launch_bounds__(256, 2) void gemm_mma_kernel() {
    extern __shared__ __half sm[];
    const uint32_t smaddr = smem_u32(sm);

    const int tid  = threadIdx.x;
    const int lane = tid & 31;
    const int wid  = tid >> 5;
    const int warp_m = wid & 3;
    const int warp_n = wid >> 2;
    const int quad  = lane >> 2;
    const int tig   = lane & 3;

    const int m0 = blockIdx.y * TILE_M;
    const int n0 = blockIdx.x * TILE_N;

    const __half* xh = (const __half*)g_xhi;
    const __half* xl = (const __half*)g_xlo;
    const __half* wt = (const __half*)g_wt;

    float acc[2][8][4];
    #pragma unroll
    for (int i = 0; i < 2; i++)
        #pragma unroll
        for (int j = 0; j < 8; j++)
            #pragma unroll
            for (int c = 0; c < 4; c++) acc[i][j][c] = 0.f;

    // ldmatrix per-lane address components (in f16 elements)
    const int a_row = lane & 15;
    const int a_k   = (lane & 16) ? 8 : 0;
    const int a_base = (warp_m * 32 + a_row) * SSTR + a_k;
    const int b_row = ((lane >> 4) & 1) * 8 + (lane & 7);
    const int b_k   = (lane & 8) ? 8 : 0;
    const int b_base = (warp_n * 64 + b_row) * SSTR + b_k;

    auto load_stage = [&](int s, int chunk) {
        const int k0 = chunk * TK;
        __half* st = sm + s * STAGE;
        #pragma unroll
        for (int r = 0; r < 2; r++) {
            int idx = tid + 256 * r;
            int row = idx >> 2;
            int c   = idx & 3;
            int gr  = m0 + row; if (gr >= N_NODES) gr = 0;
            size_t aoff = (size_t)gr * IN_DIM + k0 + c * 8;
            size_t boff = (size_t)(n0 + row) * IN_DIM + k0 + c * 8;
            __half* d = st + row * SSTR + c * 8;
            cp16(d,           xh + aoff);
            cp16(d + OFF_ALO, xl + aoff);
            cp16(d + OFF_B,   wt + boff);
        }
    };

    load_stage(0, 0);
    asm volatile("cp.async.commit_group;" ::: "memory");

    for (int chunk = 0; chunk < NCHUNK; chunk++) {
        if (chunk + 1 < NCHUNK) load_stage((chunk + 1) & 1, chunk + 1);
        asm volatile("cp.async.commit_group;" ::: "memory");
        asm volatile("cp.async.wait_group 1;" ::: "memory");
        __syncthreads();

        const uint32_t stg = smaddr + (uint32_t)(chunk & 1) * (STAGE * 2);

        #pragma unroll
        for (int ks = 0; ks < 2; ks++) {
            const int kb = ks * 16;
            uint32_t ahi[2][4], alo[2][4];
            #pragma unroll
            for (int i = 0; i < 2; i++) {
                uint32_t aa = stg + (uint32_t)(a_base + i * 16 * SSTR + kb) * 2;
                ldsm_x4(ahi[i], aa);
                ldsm_x4(alo[i], aa + OFF_ALO * 2);
            }
            #pragma unroll
            for (int p = 0; p < 4; p++) {
                uint32_t ba = stg + (uint32_t)(b_base + p * 16 * SSTR + kb) * 2;
                uint32_t bh[4];
                ldsm_x4(bh, ba + OFF_B * 2);
                // pass-major: 4 independent accs per pass
                mma_f16(acc[0][2 * p],     ahi[0], bh[0], bh[1]);   // xh*W
                mma_f16(acc[1][2 * p],     ahi[1], bh[0], bh[1]);
                mma_f16(acc[0][2 * p + 1], ahi[0], bh[2], bh[3]);
                mma_f16(acc[1][2 * p + 1], ahi[1], bh[2], bh[3]);
                mma_f16(acc[0][2 * p],     alo[0], bh[0], bh[1]);   // xl*W
                mma_f16(acc[1][2 * p],     alo[1], bh[0], bh[1]);
                mma_f16(acc[0][2 * p + 1], alo[0], bh[2], bh[3]);
                mma_f16(acc[1][2 * p + 1], alo[1], bh[2], bh[3]);
            }
        }
        __syncthreads();
    }

    // ---- epilogue: store hs (dinv already folded) ------------------------
    #pragma unroll
    for (int i = 0; i < 2; i++) {
        const int r0 = m0 + warp_m * 32 + i * 16 + quad;
        const int r1 = r0 + 8;
        const bool v0 = r0 < N_NODES;
        const bool v1 = r1 < N_NODES;
        #pragma unroll
        for (int j = 0; j < 8; j++) {
            const int col = n0 + warp_n * 64 + j * 8 + tig * 2;
            if (v0) {
                float2 s = make_float2(acc[i][j][0], acc[i][j][1]);
                *(float2*)((float*)g_hs + (size_t)r0 * HID + col) = s;
            }
            if (v1) {
                float2 s = make_float2(acc[i][j][2], acc[i][j][3]);
                *(float2*)((float*)g_hs + (size_t)r1 * HID + col) = s;
            }
        }
    }
}

// --- gather + relu + pool: one node per 64 threads, unroll 8 ----------------
__global__ __launch_bounds__(256) void gather_pool_kernel(
    const int* __restrict__ batch, const float* __restrict__ b)
{
    int t = blockIdx.x * blockDim.x + threadIdx.x;
    int n = t >> 6;
    int lane = t & 63;
    if (n >= N_NODES) return;

    int cnt = g_cnt[n];
    if (cnt > CSR_CAP) cnt = CSR_CAP;
    const int* lst = g_csr + n * CSR_CAP;

    float4 a = g_hs[(size_t)n * HID4 + lane];   // self loop
    int i = 0;
    for (; i + 8 <= cnt; i += 8) {
        int s[8];
        #pragma unroll
        for (int q = 0; q < 8; q++) s[q] = __ldg(&lst[i + q]);
        float4 v[8];
        #pragma unroll
        for (int q = 0; q < 8; q++) v[q] = __ldg(&g_hs[(size_t)s[q] * HID4 + lane]);
        #pragma unroll
        for (int q = 0; q < 8; q++) {
            a.x += v[q].x; a.y += v[q].y; a.z += v[q].z; a.w += v[q].w;
        }
    }
    for (; i < cnt; i++) {
        int s = __ldg(&lst[i]);
        float4 v = __ldg(&g_hs[(size_t)s * HID4 + lane]);
        a.x += v.x; a.y += v.y; a.z += v.z; a.w += v.w;
    }

    float d = g_dinv[n];
    float4 bb = __ldg((const float4*)b + lane);
    float4 v;
    v.x = fmaxf(fmaf(a.x, d, bb.x), 0.f);
    v.y = fmaxf(fmaf(a.y, d, bb.y), 0.f);
    v.z = fmaxf(fmaf(a.z, d, bb.z), 0.f);
    v.w = fmaxf(fmaf(a.w, d, bb.w), 0.f);

    int g = __ldg(&batch[n]);
    red_add_v4(&g_pooled[(size_t)g * HID4 + lane], v);
    if (lane == 0) atomicAdd(&g_counts[g], 1.f);
}

// --- head --------------------------------------------------------------------
__global__ void head_kernel(
    const float* __restrict__ lin_w, const float* __restrict__ lin_b,
    float* __restrict__ out)
{
    __shared__ float red[256];
    int g = blockIdx.x;
    int t = threadIdx.x;
    const float* pooled = (const float*)g_pooled;
    red[t] = pooled[g * HID + t] * __ldg(&lin_w[t]);
    __syncthreads();
    #pragma unroll
    for (int s = 128; s > 0; s >>= 1) {
        if (t < s) red[t] += red[t + s];
        __syncthreads();
    }
    if (t == 0) {
        float cnt = fmaxf(g_counts[g], 1.f);
        float z = red[0] / cnt + __ldg(&lin_b[0]);
        out[g] = 1.f / (1.f + expf(-z));
    }
}

// ---------------------------------------------------------------------------
extern "C" void kernel_launch(void* const* d_in, const int* in_sizes, int n_in,
                              void* d_out, int out_size) {
    const float* x     = (const float*)d_in[0];
    const int*   ei    = (const int*)d_in[1];
    const int*   batch = (const int*)d_in[2];
    const float* W     = (const float*)d_in[3];
    const float* b     = (const float*)d_in[4];
    const float* lin_w = (const float*)d_in[5];
    const float* lin_b = (const float*)d_in[6];
    float*       out   = (float*)d_out;

    static bool attr_set = false;
    if (!attr_set) {
        cudaFuncSetAttribute(gemm_mma_kernel,
                             cudaFuncAttributeMaxDynamicSharedMemorySize, SMEM_BYTES);
        attr_set = true;
    }

    init_kernel<<<(N_GRAPHS * HID + 255) / 256, 256>>>();
    edge_bin_kernel<<<(N_EDGES + 255) / 256, 256>>>(ei);
    dinv_kernel<<<(N_NODES + 255) / 256, 256>>>();
    convert_x_kernel<<<(N_NODES * IN_DIM / 4 + 255) / 256, 256>>>((const float4*)x);
    convert_w_kernel<<<(IN_DIM * HID / 4 + 255) / 256, 256>>>((const float4*)W);
    gemm_mma_kernel<<<dim3(HID / TILE_N, (N_NODES + TILE_M - 1) / TILE_M),
                      256, SMEM_BYTES>>>();
    gather_pool_kernel<<<(N_NODES * 64 + 255) / 256, 256>>>(batch, b);
    head_kernel<<<N_GRAPHS, 256>>>(lin_w, lin_b, out);
}

// round 12
// speedup vs baseline: 1.5816x; 1.4399x over previous
#include <cuda_runtime.h>
#include <cuda_fp16.h>
#include <cstdint>
#include <cstring>

// ---------------------------------------------------------------------------
// SyntaxGCN: GCNConv(512->256) + relu + global_mean_pool + linear(256->1) + sigmoid
// R12: full fp16 datapath (calibrated by R11's measured error washout):
//   xs = fp16(x*dinv), Wf = fp16(W):  hs = fp16(xs @ Wf)   [single MMA pass]
//   gather/pool reads fp16 hs (halves L2 traffic), accumulates fp32.
//   R11 measured: one fp16-rounding source -> 2.7e-6 final rel err; three
//   sources => ~1e-5..1e-4, far under the 1e-3 tolerance.
// ---------------------------------------------------------------------------

constexpr int N_NODES  = 20000;
constexpr int N_EDGES  = 320000;
constexpr int IN_DIM   = 512;
constexpr int HID      = 256;
constexpr int N_GRAPHS = 256;
constexpr int CSR_CAP  = 128;

constexpr int TILE_M = 128;
constexpr int TILE_N = 128;
constexpr int TK     = 32;
constexpr int NCHUNK = IN_DIM / TK;        // 16
constexpr int SSTR   = 40;                 // smem row stride in f16 (80B, LDSM conflict-free)
constexpr int MAT    = TILE_M * SSTR;      // 5120
constexpr int OFF_B  = MAT;
constexpr int STAGE  = 2 * MAT;            // 10240 f16 = 20.5KB
constexpr int SMEM_BYTES = 2 * STAGE * (int)sizeof(__half);  // 40960

// Scratch (device globals)
__device__ uint2  g_hsh[N_NODES * HID / 4];      // hs in fp16 (half2 pairs)
__device__ float  g_dinv[N_NODES];
__device__ int    g_cnt[N_NODES];
__device__ int    g_csr[N_NODES * CSR_CAP];
__device__ float4 g_pooled[N_GRAPHS * HID / 4];
__device__ float  g_counts[N_GRAPHS];
__device__ uint4  g_xh[N_NODES * IN_DIM / 8];    // fp16 x, pre-scaled by dinv
__device__ uint4  g_wt[HID * IN_DIM / 8];        // fp16 W, transposed [n][k]

// ---------------- helpers ---------------------------------------------------
__device__ __forceinline__ void red_add_v4(float4* addr, float4 v) {
    asm volatile("red.global.add.v4.f32 [%0], {%1,%2,%3,%4};"
                 :: "l"(addr), "f"(v.x), "f"(v.y), "f"(v.z), "f"(v.w)
                 : "memory");
}

__device__ __forceinline__ uint32_t smem_u32(const void* p) {
    uint32_t a;
    asm("{ .reg .u64 t; cvta.to.shared.u64 t, %1; cvt.u32.u64 %0, t; }" : "=r"(a) : "l"(p));
    return a;
}

__device__ __forceinline__ void cp16(void* dst_smem, const void* src) {
    asm volatile("cp.async.ca.shared.global [%0], [%1], 16;"
                 :: "r"(smem_u32(dst_smem)), "l"(src) : "memory");
}

__device__ __forceinline__ void ldsm_x4(uint32_t* r, uint32_t addr) {
    asm volatile("ldmatrix.sync.aligned.m8n8.x4.shared.b16 {%0,%1,%2,%3}, [%4];"
                 : "=r"(r[0]), "=r"(r[1]), "=r"(r[2]), "=r"(r[3]) : "r"(addr));
}

__device__ __forceinline__ void mma_f16(float* c, const uint32_t* a,
                                        uint32_t b0, uint32_t b1) {
    asm volatile(
        "mma.sync.aligned.m16n8k16.row.col.f32.f16.f16.f32 "
        "{%0,%1,%2,%3}, {%4,%5,%6,%7}, {%8,%9}, {%0,%1,%2,%3};"
        : "+f"(c[0]), "+f"(c[1]), "+f"(c[2]), "+f"(c[3])
        : "r"(a[0]), "r"(a[1]), "r"(a[2]), "r"(a[3]), "r"(b0), "r"(b1));
}

__device__ __forceinline__ uint32_t f2h2(float a, float b) {
    __half2 h = __halves2half2(__float2half_rn(a), __float2half_rn(b));
    uint32_t u; memcpy(&u, &h, 4);
    return u;
}

// --- init -------------------------------------------------------------------
__global__ void init_kernel() {
    int i = blockIdx.x * blockDim.x + threadIdx.x;
    if (i < N_GRAPHS * HID / 4) g_pooled[i] = make_float4(0.f, 0.f, 0.f, 0.f);
    if (i < N_GRAPHS)           g_counts[i] = 0.f;
    if (i < N_NODES)            g_cnt[i] = 0;
}

__global__ void edge_bin_kernel(const int* __restrict__ ei) {
    int e = blockIdx.x * blockDim.x + threadIdx.x;
    if (e >= N_EDGES) return;
    int src = __ldg(&ei[e]);
    int dst = __ldg(&ei[N_EDGES + e]);
    int pos = atomicAdd(&g_cnt[dst], 1);
    if (pos < CSR_CAP) g_csr[dst * CSR_CAP + pos] = src;
}

__global__ void dinv_kernel() {
    int n = blockIdx.x * blockDim.x + threadIdx.x;
    if (n < N_NODES) g_dinv[n] = rsqrtf((float)(g_cnt[n] + 1));
}

// --- preconvert xs = fp16(x*dinv) -------------------------------------------
__global__ __launch_bounds__(256) void convert_x_kernel(const float4* __restrict__ X4) {
    int i = blockIdx.x * blockDim.x + threadIdx.x;
    if (i >= N_NODES * IN_DIM / 4) return;
    int row = i >> 7;                       // IN_DIM/4 = 128 float4 per row
    float d = __ldg(&g_dinv[row]);
    float4 v = X4[i];
    uint2 o;
    o.x = f2h2(v.x * d, v.y * d);
    o.y = f2h2(v.z * d, v.w * d);
    ((uint2*)g_xh)[i] = o;
}

// --- preconvert W -> transposed fp16 [n][k] ---------------------------------
__global__ __launch_bounds__(256) void convert_w_kernel(const float4* __restrict__ W4) {
    int i = blockIdx.x * blockDim.x + threadIdx.x;
    if (i >= IN_DIM * HID / 4) return;
    int k  = i >> 6;
    int n4 = i & 63;
    float4 v = W4[i];
    float f[4] = {v.x, v.y, v.z, v.w};
    __half* wt = (__half*)g_wt;
    #pragma unroll
    for (int j = 0; j < 4; j++)
        wt[(size_t)(n4 * 4 + j) * IN_DIM + k] = __float2half_rn(f[j]);
}

// --- tensor-core GEMM: hs = fp16(xs @ W) ------------------------------------
// 256 threads, 8 warps (4m x 2n), warp tile 32x64, 2-stage cp.async, ldmatrix.
__global__ __launch_bounds__(256, 2) void gemm_mma_kernel() {
    extern __shared__ __half sm[];
    const uint32_t smaddr = smem_u32(sm);

    const int tid  = threadIdx.x;
    const int lane = tid & 31;
    const int wid  = tid >> 5;
    const int warp_m = wid & 3;
    const int warp_n = wid >> 2;
    const int quad  = lane >> 2;
    const int tig   = lane & 3;

    const int m0 = blockIdx.y * TILE_M;
    const int n0 = blockIdx.x * TILE_N;

    const __half* xh = (const __half*)g_xh;
    const __half* wt = (const __half*)g_wt;

    float acc[2][8][4];
    #pragma unroll
    for (int i = 0; i < 2; i++)
        #pragma unroll
        for (int j = 0; j < 8; j++)
            #pragma unroll
            for (int c = 0; c < 4; c++) acc[i][j][c] = 0.f;

    // ldmatrix per-lane address components (in f16 elements)
    const int a_row = lane & 15;
    const int a_k   = (lane & 16) ? 8 : 0;
    const int a_base = (warp_m * 32 + a_row) * SSTR + a_k;
    const int b_row = ((lane >> 4) & 1) * 8 + (lane & 7);
    const int b_k   = (lane & 8) ? 8 : 0;
    const int b_base = (warp_n * 64 + b_row) * SSTR + b_k;

    auto load_stage = [&](int s, int chunk) {
        const int k0 = chunk * TK;
        __half* st = sm + s * STAGE;
        #pragma unroll
        for (int r = 0; r < 2; r++) {
            int idx = tid + 256 * r;
            int row = idx >> 2;
            int c   = idx & 3;
            int gr  = m0 + row; if (gr >= N_NODES) gr = 0;
            size_t aoff = (size_t)gr * IN_DIM + k0 + c * 8;
            size_t boff = (size_t)(n0 + row) * IN_DIM + k0 + c * 8;
            __half* d = st + row * SSTR + c * 8;
            cp16(d,         xh + aoff);
            cp16(d + OFF_B, wt + boff);
        }
    };

    load_stage(0, 0);
    asm volatile("cp.async.commit_group;" ::: "memory");

    for (int chunk = 0; chunk < NCHUNK; chunk++) {
        if (chunk + 1 < NCHUNK) load_stage((chunk + 1) & 1, chunk + 1);
        asm volatile("cp.async.commit_group;" ::: "memory");
        asm volatile("cp.async.wait_group 1;" ::: "memory");
        __syncthreads();

        const uint32_t stg = smaddr + (uint32_t)(chunk & 1) * (STAGE * 2);

        #pragma unroll
        for (int ks = 0; ks < 2; ks++) {
            const int kb = ks * 16;
            uint32_t a0[4], a1[4];
            uint32_t aa = stg + (uint32_t)(a_base + kb) * 2;
            ldsm_x4(a0, aa);
            ldsm_x4(a1, aa + 16 * SSTR * 2);
            #pragma unroll
            for (int p = 0; p < 4; p++) {
                uint32_t ba = stg + (uint32_t)(b_base + p * 16 * SSTR + kb) * 2;
                uint32_t bh[4];
                ldsm_x4(bh, ba + OFF_B * 2);
                mma_f16(acc[0][2 * p],     a0, bh[0], bh[1]);
                mma_f16(acc[1][2 * p],     a1, bh[0], bh[1]);
                mma_f16(acc[0][2 * p + 1], a0, bh[2], bh[3]);
                mma_f16(acc[1][2 * p + 1], a1, bh[2], bh[3]);
            }
        }
        __syncthreads();
    }

    // ---- epilogue: store hs as fp16 (half2 per acc pair) ------------------
    __half* hsh = (__half*)g_hsh;
    #pragma unroll
    for (int i = 0; i < 2; i++) {
        const int r0 = m0 + warp_m * 32 + i * 16 + quad;
        const int r1 = r0 + 8;
        const bool v0 = r0 < N_NODES;
        const bool v1 = r1 < N_NODES;
        #pragma unroll
        for (int j = 0; j < 8; j++) {
            const int col = n0 + warp_n * 64 + j * 8 + tig * 2;
            if (v0)
                *(uint32_t*)(hsh + (size_t)r0 * HID + col) = f2h2(acc[i][j][0], acc[i][j][1]);
            if (v1)
                *(uint32_t*)(hsh + (size_t)r1 * HID + col) = f2h2(acc[i][j][2], acc[i][j][3]);
        }
    }
}

// --- gather + relu + pool: one node per 64 threads, fp16 rows ---------------
__global__ __launch_bounds__(256) void gather_pool_kernel(
    const int* __restrict__ batch, const float* __restrict__ b)
{
    int t = blockIdx.x * blockDim.x + threadIdx.x;
    int n = t >> 6;
    int lane = t & 63;
    if (n >= N_NODES) return;

    int cnt = g_cnt[n];
    if (cnt > CSR_CAP) cnt = CSR_CAP;
    const int* lst = g_csr + n * CSR_CAP;

    auto addrow = [&](float4& a, uint2 raw) {
        __half2 p0, p1;
        memcpy(&p0, &raw.x, 4);
        memcpy(&p1, &raw.y, 4);
        float2 f0 = __half22float2(p0);
        float2 f1 = __half22float2(p1);
        a.x += f0.x; a.y += f0.y; a.z += f1.x; a.w += f1.y;
    };

    float4 a = make_float4(0.f, 0.f, 0.f, 0.f);
    addrow(a, __ldg(&g_hsh[(size_t)n * 64 + lane]));   // self loop

    int i = 0;
    for (; i + 8 <= cnt; i += 8) {
        int s[8];
        #pragma unroll
        for (int q = 0; q < 8; q++) s[q] = __ldg(&lst[i + q]);
        uint2 v[8];
        #pragma unroll
        for (int q = 0; q < 8; q++) v[q] = __ldg(&g_hsh[(size_t)s[q] * 64 + lane]);
        #pragma unroll
        for (int q = 0; q < 8; q++) addrow(a, v[q]);
    }
    for (; i < cnt; i++) {
        int s = __ldg(&lst[i]);
        addrow(a, __ldg(&g_hsh[(size_t)s * 64 + lane]));
    }

    float d = g_dinv[n];
    float4 bb = __ldg((const float4*)b + lane);
    float4 v;
    v.x = fmaxf(fmaf(a.x, d, bb.x), 0.f);
    v.y = fmaxf(fmaf(a.y, d, bb.y), 0.f);
    v.z = fmaxf(fmaf(a.z, d, bb.z), 0.f);
    v.w = fmaxf(fmaf(a.w, d, bb.w), 0.f);

    int g = __ldg(&batch[n]);
    red_add_v4(&g_pooled[(size_t)g * 64 + lane], v);
    if (lane == 0) atomicAdd(&g_counts[g], 1.f);
}

// --- head --------------------------------------------------------------------
__global__ void head_kernel(
    const float* __restrict__ lin_w, const float* __restrict__ lin_b,
    float* __restrict__ out)
{
    __shared__ float red[256];
    int g = blockIdx.x;
    int t = threadIdx.x;
    const float* pooled = (const float*)g_pooled;
    red[t] = pooled[g * HID + t] * __ldg(&lin_w[t]);
    __syncthreads();
    #pragma unroll
    for (int s = 128; s > 0; s >>= 1) {
        if (t < s) red[t] += red[t + s];
        __syncthreads();
    }
    if (t == 0) {
        float cnt = fmaxf(g_counts[g], 1.f);
        float z = red[0] / cnt + __ldg(&lin_b[0]);
        out[g] = 1.f / (1.f + expf(-z));
    }
}

// ---------------------------------------------------------------------------
extern "C" void kernel_launch(void* const* d_in, const int* in_sizes, int n_in,
                              void* d_out, int out_size) {
    const float* x     = (const float*)d_in[0];
    const int*   ei    = (const int*)d_in[1];
    const int*   batch = (const int*)d_in[2];
    const float* W     = (const float*)d_in[3];
    const float* b     = (const float*)d_in[4];
    const float* lin_w = (const float*)d_in[5];
    const float* lin_b = (const float*)d_in[6];
    float*       out   = (float*)d_out;

    static bool attr_set = false;
    if (!attr_set) {
        cudaFuncSetAttribute(gemm_mma_kernel,
                             cudaFuncAttributeMaxDynamicSharedMemorySize, SMEM_BYTES);
        attr_set = true;
    }

    init_kernel<<<(N_GRAPHS * HID + 255) / 256, 256>>>();
    edge_bin_kernel<<<(N_EDGES + 255) / 256, 256>>>(ei);
    dinv_kernel<<<(N_NODES + 255) / 256, 256>>>();
    convert_x_kernel<<<(N_NODES * IN_DIM / 4 + 255) / 256, 256>>>((const float4*)x);
    convert_w_kernel<<<(IN_DIM * HID / 4 + 255) / 256, 256>>>((const float4*)W);
    gemm_mma_kernel<<<dim3(HID / TILE_N, (N_NODES + TILE_M - 1) / TILE_M),
                      256, SMEM_BYTES>>>();
    gather_pool_kernel<<<(N_NODES * 64 + 255) / 256, 256>>>(batch, b);
    head_kernel<<<N_GRAPHS, 256>>>(lin_w, lin_b, out);
}